// round 15
// baseline (speedup 1.0000x reference)
#include <cuda_runtime.h>
#include <math.h>

// ---------------------------------------------------------------------------
// LSForward: Born-series scattering, M=4096 pts, 4 wavenumbers (0.5*m), 5 iters.
// R14 = R13 (acc at the 3-reg FFMA issue ceiling; fma 50.2% of rt=1 peak)
// with the non-acc tail attacked:
//   (1) JSPLIT 64->32 / ROWBLK 16->32 (RPT=1): acc grid & per-pair fma ops
//       unchanged, but partials halve (4MB) and k_update sums 32 not 64
//       L2 loads per element (-~4us over 5 iters). LDS/pair doubles but
//       rides the MIO pipe (non-binding; issue has headroom).
//   (2) k_init parallelized 4x over (i,m) - same accurate sincosf math.
//   (3) PDL + unroll-8 acc body + scalar update retained (all measured).
// e-computation rounding is LOAD-BEARING (R4/R7 failure mode) - untouched.
// ---------------------------------------------------------------------------

constexpr int M_PTS  = 4096;
constexpr int NDOBS  = 64;
constexpr int NK     = 4;
constexpr int N_ITER = 5;

constexpr int TPB    = 128;                    // threads per block
constexpr int ROWBLK = 32;                     // row-blocks (128 rows each)
constexpr int JSPLIT = 32;                     // j-partition count (grid.y)
constexpr int JCHUNK = M_PTS / JSPLIT;         // 128 j's per block

constexpr float C_G = 0.07957747154594767f;    // 1/(4*pi)

// Scratch (allocation-free: __device__ globals)
__device__ float g_px[M_PTS], g_py[M_PTS], g_pz[M_PTS];
__device__ float g_r2q[M_PTS];                     // 0.25*|p|^2
__device__ float g_vw[M_PTS];                      // 0.5*C_G * V * w (folded)
__device__ float g_p0[NK * 2 * M_PTS];
__device__ float g_p [NK * 2 * M_PTS];
__device__ float g_a [NK * 2 * M_PTS];             // folded matvec input
__device__ float g_part[JSPLIT][NK * 2 * M_PTS];   // deterministic j-partials (4 MB)

__device__ __forceinline__ float fsqrt_approx(float x) {
    float r; asm("sqrt.approx.f32 %0,%1;" : "=f"(r) : "f"(x)); return r;
}
__device__ __forceinline__ void pdl_wait() {
#if __CUDA_ARCH__ >= 900
    cudaGridDependencySynchronize();
#endif
}

// ---------------------------------------------------------------------------
// Init, 4x parallel over (i, m): 16384 threads. Scalar per-point fields are
// written by the m==0 thread only; all math identical to R13's init.
// ---------------------------------------------------------------------------
__global__ void k_init(const float* __restrict__ V,
                       const float* __restrict__ pts,
                       const float* __restrict__ w) {
    int idx = blockIdx.x * blockDim.x + threadIdx.x;   // 0 .. 4*M-1
    if (idx >= NK * M_PTS) return;
    int i = idx >> 2;
    int m = idx & 3;
    float x = pts[3 * i], y = pts[3 * i + 1], z = pts[3 * i + 2];
    float vw = 0.5f * C_G * V[i] * w[i];
    if (m == 0) {
        g_px[i] = x; g_py[i] = y; g_pz[i] = z;
        g_r2q[i] = 0.25f * (x * x + y * y + z * z);
        g_vw[i] = vw;
    }
    float kv = 0.5f * (float)(m + 1);
    float s, c;
    sincosf(kv * z, &s, &c);                   // accurate; one-time cost
    g_p0[m * 2 * M_PTS + i]          = c;
    g_p0[m * 2 * M_PTS + M_PTS + i]  = s;
    g_p [m * 2 * M_PTS + i]          = c;
    g_p [m * 2 * M_PTS + M_PTS + i]  = s;
    g_a [m * 2 * M_PTS + i]          = vw * c;
    g_a [m * 2 * M_PTS + M_PTS + i]  = vw * s;
}

// ---------------------------------------------------------------------------
// Core Born matvec: grid (ROWBLK, JSPLIT) = (32, 32), 128 rows x 128 j per
// block, RPT=1. Per pair: e = 0.25*d2 (R3-exact form: dot first, then ONE
// fused -0.5*dot + r2sum — rounding is load-bearing near coincident points);
// theta = sqrt(e) = 0.5*D; sc = rsqrt(e) = 2/D with 0.5*C_G prefolded in a.
// Chebyshev G_m = sc * exp(i*m*theta).
// ---------------------------------------------------------------------------
__global__ __launch_bounds__(TPB) void k_acc() {
    __shared__ alignas(16) float sj[JCHUNK][12];  // px,py,pz,r2q, ar0,ai0..ar3,ai3

    pdl_wait();                                   // g_a/g_px from predecessor

    int t  = threadIdx.x;
    int j0 = blockIdx.y * JCHUNK;

    {
        int j = j0 + t;                           // JCHUNK == TPB == 128
        sj[t][0] = g_px[j];
        sj[t][1] = g_py[j];
        sj[t][2] = g_pz[j];
        sj[t][3] = g_r2q[j];
#pragma unroll
        for (int m = 0; m < NK; m++) {
            sj[t][4 + 2 * m] = g_a[m * 2 * M_PTS + j];
            sj[t][5 + 2 * m] = g_a[m * 2 * M_PTS + M_PTS + j];
        }
    }
    __syncthreads();

    int row = blockIdx.x * TPB + t;
    float pix = g_px[row], piy = g_py[row], piz = g_pz[row], r2i = g_r2q[row];

    float accr[NK], acci[NK];
#pragma unroll
    for (int m = 0; m < NK; m++) { accr[m] = 0.f; acci[m] = 0.f; }

#pragma unroll 8
    for (int jj = 0; jj < JCHUNK; jj++) {
        float4 P  = *reinterpret_cast<const float4*>(&sj[jj][0]);
        float4 A0 = *reinterpret_cast<const float4*>(&sj[jj][4]);
        float4 A1 = *reinterpret_cast<const float4*>(&sj[jj][8]);
        int jg = j0 + jj;

        float dot = fmaf(pix, P.x, fmaf(piy, P.y, piz * P.z));
        float e   = fmaf(-0.5f, dot, r2i + P.w);        // 0.25 * d2
        e = fmaxf(e, 2.5e-13f);
        float th  = fsqrt_approx(e);                    // 0.5 * D
        float sc  = rsqrtf(e);                          // 2/D (scale in a)
        sc = (row == jg) ? 0.f : sc;
        float s1, c1;
        __sincosf(th, &s1, &c1);
        float tc  = c1 + c1;
        // Chebyshev: G_m = sc * exp(i m theta)
        float g1r = sc * c1,             g1i = sc * s1;
        float g2r = fmaf(tc, g1r, -sc);  float g2i = tc * g1i;
        float g3r = fmaf(tc, g2r, -g1r); float g3i = fmaf(tc, g2i, -g1i);
        float g4r = fmaf(tc, g3r, -g2r); float g4i = fmaf(tc, g3i, -g2i);
        // complex MAC (negations free in FFMA modifiers)
        accr[0] = fmaf(g1r, A0.x, fmaf(-g1i, A0.y, accr[0]));
        acci[0] = fmaf(g1r, A0.y, fmaf( g1i, A0.x, acci[0]));
        accr[1] = fmaf(g2r, A0.z, fmaf(-g2i, A0.w, accr[1]));
        acci[1] = fmaf(g2r, A0.w, fmaf( g2i, A0.z, acci[1]));
        accr[2] = fmaf(g3r, A1.x, fmaf(-g3i, A1.y, accr[2]));
        acci[2] = fmaf(g3r, A1.y, fmaf( g3i, A1.x, acci[2]));
        accr[3] = fmaf(g4r, A1.z, fmaf(-g4i, A1.w, accr[3]));
        acci[3] = fmaf(g4r, A1.w, fmaf( g4i, A1.z, acci[3]));
    }

    float* part = g_part[blockIdx.y];
#pragma unroll
    for (int m = 0; m < NK; m++) {
        part[m * 2 * M_PTS + row]         = accr[m];
        part[m * 2 * M_PTS + M_PTS + row] = acci[m];
    }
}

// ---------------------------------------------------------------------------
// Deterministic partial reduction + Born update: p = p0 + sum; a = vw*p.
// SCALAR: 32768 threads / 128 blocks — thread-count parallelism hides the
// L2 latency; now only 32 loads per element.
// ---------------------------------------------------------------------------
__global__ void k_update() {
    pdl_wait();                                  // g_part from k_acc
    int e = blockIdx.x * blockDim.x + threadIdx.x;  // 0 .. NK*2*M-1
    float s = 0.f;
#pragma unroll 8
    for (int js = 0; js < JSPLIT; js++) s += g_part[js][e];
    float pv = g_p0[e] + s;
    g_p[e] = pv;
    g_a[e] = g_vw[e & (M_PTS - 1)] * pv;         // vw already 0.5*C_G*V*w
}

// ---------------------------------------------------------------------------
// Far-field: one block per observation direction.
// ---------------------------------------------------------------------------
__global__ __launch_bounds__(256) void k_far(const float* __restrict__ V,
                                             const float* __restrict__ obs,
                                             const float* __restrict__ w,
                                             float* __restrict__ out) {
    constexpr int FTPB = 256;
    pdl_wait();                                  // g_p from final k_update
    int d = blockIdx.x;
    int t = threadIdx.x;
    float ox = obs[3 * d], oy = obs[3 * d + 1], oz = obs[3 * d + 2];

    float fr[NK] = {0.f, 0.f, 0.f, 0.f};
    float fi[NK] = {0.f, 0.f, 0.f, 0.f};

    for (int j = t; j < M_PTS; j += FTPB) {
        float q = fmaf(g_px[j], ox, fmaf(g_py[j], oy, g_pz[j] * oz));
        float s1, c1;
        __sincosf(0.5f * q, &s1, &c1);
        float tc = c1 + c1;
        float cm[NK], sm[NK];
        cm[0] = c1;                      sm[0] = s1;
        cm[1] = fmaf(tc, c1, -1.f);      sm[1] = tc * s1;
        cm[2] = fmaf(tc, cm[1], -cm[0]); sm[2] = fmaf(tc, sm[1], -sm[0]);
        cm[3] = fmaf(tc, cm[2], -cm[1]); sm[3] = fmaf(tc, sm[2], -sm[1]);
        float v = V[j], wj = w[j];
#pragma unroll
        for (int m = 0; m < NK; m++) {
            float pr = g_p[m * 2 * M_PTS + j];
            float pi = g_p[m * 2 * M_PTS + M_PTS + j];
            float zr = v * pr, zi = v * pi;
            float ir = fmaf(zr, cm[m],  zi * sm[m]);   // exp(-ikQ)
            float ii = fmaf(zi, cm[m], -zr * sm[m]);
            fr[m] = fmaf(wj, ir, fr[m]);
            fi[m] = fmaf(wj, ii, fi[m]);
        }
    }

#pragma unroll
    for (int off = 16; off; off >>= 1) {
#pragma unroll
        for (int m = 0; m < NK; m++) {
            fr[m] += __shfl_down_sync(0xffffffffu, fr[m], off);
            fi[m] += __shfl_down_sync(0xffffffffu, fi[m], off);
        }
    }
    __shared__ float sred[8][FTPB / 32];
    int lane = t & 31, wid = t >> 5;
    if (lane == 0) {
#pragma unroll
        for (int m = 0; m < NK; m++) {
            sred[2 * m][wid]     = fr[m];
            sred[2 * m + 1][wid] = fi[m];
        }
    }
    __syncthreads();
    if (t < 8) {
        float s = 0.f;
#pragma unroll
        for (int wdx = 0; wdx < FTPB / 32; wdx++) s += sred[t][wdx];
        int m = t >> 1, c = t & 1;
        out[m * NDOBS * 2 + d * 2 + c] = -C_G * s;
    }
}

// ---------------------------------------------------------------------------
template <typename K, typename... Args>
static inline void launch_pdl(K kernel, dim3 grid, dim3 block, Args... args) {
    cudaLaunchConfig_t cfg = {};
    cfg.gridDim = grid;
    cfg.blockDim = block;
    cfg.dynamicSmemBytes = 0;
    cfg.stream = 0;
    cudaLaunchAttribute at[1];
    at[0].id = cudaLaunchAttributeProgrammaticStreamSerialization;
    at[0].val.programmaticStreamSerializationAllowed = 1;
    cfg.attrs = at;
    cfg.numAttrs = 1;
    cudaLaunchKernelEx(&cfg, kernel, args...);
}

extern "C" void kernel_launch(void* const* d_in, const int* in_sizes, int n_in,
                              void* d_out, int out_size) {
    const float* V   = (const float*)d_in[0];   // [4096]
    const float* obs = (const float*)d_in[1];   // [64,3]
    const float* pts = (const float*)d_in[2];   // [4096,3]
    const float* w   = (const float*)d_in[3];   // [4096]
    float* out = (float*)d_out;                 // [4,64,2]

    k_init<<<(NK * M_PTS) / 256, 256>>>(V, pts, w);
    for (int it = 0; it < N_ITER; it++) {
        launch_pdl(k_acc, dim3(ROWBLK, JSPLIT), dim3(TPB));
        launch_pdl(k_update, dim3((NK * 2 * M_PTS) / 256), dim3(256));
    }
    launch_pdl(k_far, dim3(NDOBS), dim3(256), V, obs, w, out);
}

// round 16
// speedup vs baseline: 1.0433x; 1.0433x over previous
#include <cuda_runtime.h>
#include <math.h>

// ---------------------------------------------------------------------------
// LSForward: Born-series scattering, M=4096 pts, 4 wavenumbers (0.5*m), 5 iters.
// R16 = R13 verbatim (best: 160.2us; acc at the 3-reg FFMA issue ceiling,
// RPT=2 proven the LDS-amortization sweet spot by R14's neutral trade) with
// one micro-lever: k_update reshaped 128x256 -> 256x128 blocks (same 32768
// threads, bit-identical js-ascending sums) so all 148 SMs carry the L2-
// latency-bound reduction, + unroll 16 for per-thread MLP.
// e-computation rounding is LOAD-BEARING (R4/R7 failure mode) - untouched.
// ---------------------------------------------------------------------------

constexpr int M_PTS  = 4096;
constexpr int NDOBS  = 64;
constexpr int NK     = 4;
constexpr int N_ITER = 5;

constexpr int TPB    = 128;                    // threads per block
constexpr int RPT    = 2;                      // rows per thread
constexpr int ROWBLK = M_PTS / (TPB * RPT);    // 16 row-blocks
constexpr int JSPLIT = 64;                     // j-partition count (grid.y)
constexpr int JCHUNK = M_PTS / JSPLIT;         // 64 j's per block

constexpr float C_G = 0.07957747154594767f;    // 1/(4*pi)

// Scratch (allocation-free: __device__ globals)
__device__ float g_px[M_PTS], g_py[M_PTS], g_pz[M_PTS];
__device__ float g_r2q[M_PTS];                     // 0.25*|p|^2
__device__ float g_vw[M_PTS];                      // 0.5*C_G * V * w (folded)
__device__ float g_p0[NK * 2 * M_PTS];
__device__ float g_p [NK * 2 * M_PTS];
__device__ float g_a [NK * 2 * M_PTS];             // folded matvec input
__device__ float g_part[JSPLIT][NK * 2 * M_PTS];   // deterministic j-partials (8 MB)

__device__ __forceinline__ float fsqrt_approx(float x) {
    float r; asm("sqrt.approx.f32 %0,%1;" : "=f"(r) : "f"(x)); return r;
}
__device__ __forceinline__ void pdl_wait() {
#if __CUDA_ARCH__ >= 900
    cudaGridDependencySynchronize();
#endif
}

// ---------------------------------------------------------------------------
__global__ void k_init(const float* __restrict__ V,
                       const float* __restrict__ pts,
                       const float* __restrict__ w) {
    int i = blockIdx.x * blockDim.x + threadIdx.x;
    if (i >= M_PTS) return;
    float x = pts[3 * i], y = pts[3 * i + 1], z = pts[3 * i + 2];
    g_px[i] = x; g_py[i] = y; g_pz[i] = z;
    g_r2q[i] = 0.25f * (x * x + y * y + z * z);
    float vw = 0.5f * C_G * V[i] * w[i];
    g_vw[i] = vw;
#pragma unroll
    for (int m = 0; m < NK; m++) {
        float kv = 0.5f * (float)(m + 1);
        float s, c;
        sincosf(kv * z, &s, &c);                   // accurate; one-time cost
        g_p0[m * 2 * M_PTS + i]          = c;
        g_p0[m * 2 * M_PTS + M_PTS + i]  = s;
        g_p [m * 2 * M_PTS + i]          = c;
        g_p [m * 2 * M_PTS + M_PTS + i]  = s;
        g_a [m * 2 * M_PTS + i]          = vw * c;
        g_a [m * 2 * M_PTS + M_PTS + i]  = vw * s;
    }
}

// ---------------------------------------------------------------------------
// Core Born matvec: grid (ROWBLK, JSPLIT), 256 rows x 64 j per block, RPT=2.
// Per pair: e = 0.25*d2 (R3-exact form: dot first, then ONE fused
// -0.5*dot + r2sum — rounding is load-bearing near coincident points);
// theta = sqrt(e) = 0.5*D; sc = rsqrt(e) = 2/D with 0.5*C_G prefolded in a.
// Chebyshev G_m = sc * exp(i*m*theta).
// ---------------------------------------------------------------------------
__global__ __launch_bounds__(TPB) void k_acc() {
    __shared__ alignas(16) float sj[JCHUNK][12];  // px,py,pz,r2q, ar0,ai0..ar3,ai3

    pdl_wait();                                   // g_a/g_px from predecessor

    int t  = threadIdx.x;
    int j0 = blockIdx.y * JCHUNK;

    if (t < JCHUNK) {
        int j = j0 + t;
        sj[t][0] = g_px[j];
        sj[t][1] = g_py[j];
        sj[t][2] = g_pz[j];
        sj[t][3] = g_r2q[j];
#pragma unroll
        for (int m = 0; m < NK; m++) {
            sj[t][4 + 2 * m] = g_a[m * 2 * M_PTS + j];
            sj[t][5 + 2 * m] = g_a[m * 2 * M_PTS + M_PTS + j];
        }
    }
    __syncthreads();

    int rbase = blockIdx.x * (TPB * RPT) + t;
    float pix[RPT], piy[RPT], piz[RPT], r2i[RPT];
#pragma unroll
    for (int r = 0; r < RPT; r++) {
        int row = rbase + r * TPB;
        pix[r] = g_px[row]; piy[r] = g_py[row];
        piz[r] = g_pz[row]; r2i[r] = g_r2q[row];
    }

    float accr[RPT][NK], acci[RPT][NK];
#pragma unroll
    for (int r = 0; r < RPT; r++)
#pragma unroll
        for (int m = 0; m < NK; m++) { accr[r][m] = 0.f; acci[r][m] = 0.f; }

#pragma unroll 8
    for (int jj = 0; jj < JCHUNK; jj++) {
        float4 P  = *reinterpret_cast<const float4*>(&sj[jj][0]);
        float4 A0 = *reinterpret_cast<const float4*>(&sj[jj][4]);
        float4 A1 = *reinterpret_cast<const float4*>(&sj[jj][8]);
        int jg = j0 + jj;
#pragma unroll
        for (int r = 0; r < RPT; r++) {
            int row = rbase + r * TPB;
            float dot = fmaf(pix[r], P.x, fmaf(piy[r], P.y, piz[r] * P.z));
            float e   = fmaf(-0.5f, dot, r2i[r] + P.w);     // 0.25 * d2
            e = fmaxf(e, 2.5e-13f);
            float th  = fsqrt_approx(e);                    // 0.5 * D
            float sc  = rsqrtf(e);                          // 2/D (scale in a)
            sc = (row == jg) ? 0.f : sc;
            float s1, c1;
            __sincosf(th, &s1, &c1);
            float tc  = c1 + c1;
            // Chebyshev: G_m = sc * exp(i m theta)
            float g1r = sc * c1,             g1i = sc * s1;
            float g2r = fmaf(tc, g1r, -sc);  float g2i = tc * g1i;
            float g3r = fmaf(tc, g2r, -g1r); float g3i = fmaf(tc, g2i, -g1i);
            float g4r = fmaf(tc, g3r, -g2r); float g4i = fmaf(tc, g3i, -g2i);
            // complex MAC (negations free in FFMA modifiers)
            accr[r][0] = fmaf(g1r, A0.x, fmaf(-g1i, A0.y, accr[r][0]));
            acci[r][0] = fmaf(g1r, A0.y, fmaf( g1i, A0.x, acci[r][0]));
            accr[r][1] = fmaf(g2r, A0.z, fmaf(-g2i, A0.w, accr[r][1]));
            acci[r][1] = fmaf(g2r, A0.w, fmaf( g2i, A0.z, acci[r][1]));
            accr[r][2] = fmaf(g3r, A1.x, fmaf(-g3i, A1.y, accr[r][2]));
            acci[r][2] = fmaf(g3r, A1.y, fmaf( g3i, A1.x, acci[r][2]));
            accr[r][3] = fmaf(g4r, A1.z, fmaf(-g4i, A1.w, accr[r][3]));
            acci[r][3] = fmaf(g4r, A1.w, fmaf( g4i, A1.z, acci[r][3]));
        }
    }

    float* part = g_part[blockIdx.y];
#pragma unroll
    for (int r = 0; r < RPT; r++) {
        int row = rbase + r * TPB;
#pragma unroll
        for (int m = 0; m < NK; m++) {
            part[m * 2 * M_PTS + row]         = accr[r][m];
            part[m * 2 * M_PTS + M_PTS + row] = acci[r][m];
        }
    }
}

// ---------------------------------------------------------------------------
// Deterministic partial reduction + Born update: p = p0 + sum; a = vw*p.
// SCALAR, 256 blocks x 128 threads: same 32768 threads / bit-identical
// js-ascending sums, but spread across ALL 148 SMs (L2-latency-bound kernel:
// SM coverage == outstanding-load parallelism). Unroll 16 for per-thread MLP.
// ---------------------------------------------------------------------------
__global__ __launch_bounds__(128) void k_update() {
    pdl_wait();                                  // g_part from k_acc
    int e = blockIdx.x * blockDim.x + threadIdx.x;  // 0 .. NK*2*M-1
    float s = 0.f;
#pragma unroll 16
    for (int js = 0; js < JSPLIT; js++) s += g_part[js][e];
    float pv = g_p0[e] + s;
    g_p[e] = pv;
    g_a[e] = g_vw[e & (M_PTS - 1)] * pv;         // vw already 0.5*C_G*V*w
}

// ---------------------------------------------------------------------------
// Far-field: one block per observation direction.
// ---------------------------------------------------------------------------
__global__ __launch_bounds__(256) void k_far(const float* __restrict__ V,
                                             const float* __restrict__ obs,
                                             const float* __restrict__ w,
                                             float* __restrict__ out) {
    constexpr int FTPB = 256;
    pdl_wait();                                  // g_p from final k_update
    int d = blockIdx.x;
    int t = threadIdx.x;
    float ox = obs[3 * d], oy = obs[3 * d + 1], oz = obs[3 * d + 2];

    float fr[NK] = {0.f, 0.f, 0.f, 0.f};
    float fi[NK] = {0.f, 0.f, 0.f, 0.f};

    for (int j = t; j < M_PTS; j += FTPB) {
        float q = fmaf(g_px[j], ox, fmaf(g_py[j], oy, g_pz[j] * oz));
        float s1, c1;
        __sincosf(0.5f * q, &s1, &c1);
        float tc = c1 + c1;
        float cm[NK], sm[NK];
        cm[0] = c1;                      sm[0] = s1;
        cm[1] = fmaf(tc, c1, -1.f);      sm[1] = tc * s1;
        cm[2] = fmaf(tc, cm[1], -cm[0]); sm[2] = fmaf(tc, sm[1], -sm[0]);
        cm[3] = fmaf(tc, cm[2], -cm[1]); sm[3] = fmaf(tc, sm[2], -sm[1]);
        float v = V[j], wj = w[j];
#pragma unroll
        for (int m = 0; m < NK; m++) {
            float pr = g_p[m * 2 * M_PTS + j];
            float pi = g_p[m * 2 * M_PTS + M_PTS + j];
            float zr = v * pr, zi = v * pi;
            float ir = fmaf(zr, cm[m],  zi * sm[m]);   // exp(-ikQ)
            float ii = fmaf(zi, cm[m], -zr * sm[m]);
            fr[m] = fmaf(wj, ir, fr[m]);
            fi[m] = fmaf(wj, ii, fi[m]);
        }
    }

#pragma unroll
    for (int off = 16; off; off >>= 1) {
#pragma unroll
        for (int m = 0; m < NK; m++) {
            fr[m] += __shfl_down_sync(0xffffffffu, fr[m], off);
            fi[m] += __shfl_down_sync(0xffffffffu, fi[m], off);
        }
    }
    __shared__ float sred[8][FTPB / 32];
    int lane = t & 31, wid = t >> 5;
    if (lane == 0) {
#pragma unroll
        for (int m = 0; m < NK; m++) {
            sred[2 * m][wid]     = fr[m];
            sred[2 * m + 1][wid] = fi[m];
        }
    }
    __syncthreads();
    if (t < 8) {
        float s = 0.f;
#pragma unroll
        for (int wdx = 0; wdx < FTPB / 32; wdx++) s += sred[t][wdx];
        int m = t >> 1, c = t & 1;
        out[m * NDOBS * 2 + d * 2 + c] = -C_G * s;
    }
}

// ---------------------------------------------------------------------------
template <typename K, typename... Args>
static inline void launch_pdl(K kernel, dim3 grid, dim3 block, Args... args) {
    cudaLaunchConfig_t cfg = {};
    cfg.gridDim = grid;
    cfg.blockDim = block;
    cfg.dynamicSmemBytes = 0;
    cfg.stream = 0;
    cudaLaunchAttribute at[1];
    at[0].id = cudaLaunchAttributeProgrammaticStreamSerialization;
    at[0].val.programmaticStreamSerializationAllowed = 1;
    cfg.attrs = at;
    cfg.numAttrs = 1;
    cudaLaunchKernelEx(&cfg, kernel, args...);
}

extern "C" void kernel_launch(void* const* d_in, const int* in_sizes, int n_in,
                              void* d_out, int out_size) {
    const float* V   = (const float*)d_in[0];   // [4096]
    const float* obs = (const float*)d_in[1];   // [64,3]
    const float* pts = (const float*)d_in[2];   // [4096,3]
    const float* w   = (const float*)d_in[3];   // [4096]
    float* out = (float*)d_out;                 // [4,64,2]

    k_init<<<M_PTS / 256, 256>>>(V, pts, w);
    for (int it = 0; it < N_ITER; it++) {
        launch_pdl(k_acc, dim3(ROWBLK, JSPLIT), dim3(TPB));
        launch_pdl(k_update, dim3((NK * 2 * M_PTS) / 128), dim3(128));
    }
    launch_pdl(k_far, dim3(NDOBS), dim3(256), V, obs, w, out);
}